// round 2
// baseline (speedup 1.0000x reference)
#include <cuda_runtime.h>

// Problem constants
#define BB  32
#define LL  128
#define HH  8
#define EE  64
#define PP  16
#define GG  2          // BB / PP
#define WIN 2048

#define KPAD 68        // K row stride in floats (4-float pad: 32-way -> 4-way bank conflict)

// Group-mean series accumulator: [G, H, L, L] = 2*8*128*128 floats = 4 MB.
__device__ float g_acc[GG * HH * LL * LL];

// ---------------------------------------------------------------------------
// Kernel 0: zero the accumulator (float4 stores).
// ---------------------------------------------------------------------------
__global__ void zero_acc_kernel() {
    int i = blockIdx.x * 256 + threadIdx.x;
    ((float4*)g_acc)[i] = make_float4(0.f, 0.f, 0.f, 0.f);
}

// f32x2 packed FMA helpers (SASS FFMA2; PTX ISA 8.6, sm_100+)
__device__ __forceinline__ void ffma2(unsigned long long& acc,
                                      unsigned long long a,
                                      unsigned long long b) {
    asm("fma.rn.f32x2 %0, %1, %2, %0;" : "+l"(acc) : "l"(a), "l"(b));
}
__device__ __forceinline__ float unpack_sum(unsigned long long v) {
    float lo, hi;
    asm("mov.b64 {%0,%1}, %2;" : "=f"(lo), "=f"(hi) : "l"(v));
    return lo + hi;
}
__device__ __forceinline__ unsigned long long pack2(float lo, float hi) {
    unsigned long long v;
    asm("mov.b64 %0, {%1,%2};" : "=l"(v) : "f"(lo), "f"(hi));
    return v;
}

// ---------------------------------------------------------------------------
// Kernel 1: attention. One CTA per (b, h, row-half) -> 512 CTAs, 64 q-rows each.
//   smem floats: sK[128][68] | sV[128][64] | sQ[64][64] | sP[64][128] = 114 KB
// ---------------------------------------------------------------------------
__global__ void __launch_bounds__(256, 1) attn_kernel(
    const float* __restrict__ Q, const float* __restrict__ K,
    const float* __restrict__ V, float* __restrict__ outV)
{
    extern __shared__ float sm[];
    float* sK = sm;                          // 128 * 68 = 8704
    float* sV = sm + 8704;                   // 128 * 64 = 8192
    float* sQ = sm + 16896;                  //  64 * 64 = 4096
    float* sP = sm + 20992;                  //  64 *128 = 8192

    const int bx = blockIdx.x;
    const int b  = bx >> 4;
    const int h  = (bx >> 1) & 7;
    const int r0 = (bx & 1) * 64;            // this CTA's first query row
    const int t  = threadIdx.x;

    const size_t base = ((size_t)b * LL * HH + h) * EE;
    const float4* q4 = (const float4*)(Q + base);
    const float4* k4 = (const float4*)(K + base);
    const float4* v4 = (const float4*)(V + base);
    // Row stride in global is H*E/4 = 128 float4; 16 float4 per row.
    for (int i = t; i < 2048; i += 256) {    // K, V: 128 rows
        int row = i >> 4, c4 = i & 15;
        ((float4*)sK)[row * (KPAD / 4) + c4] = k4[row * 128 + c4];
        ((float4*)sV)[i]                     = v4[row * 128 + c4];
    }
    for (int i = t; i < 1024; i += 256) {    // Q: this CTA's 64 rows
        int row = i >> 4, c4 = i & 15;
        ((float4*)sQ)[i] = q4[(r0 + row) * 128 + c4];
    }
    __syncthreads();

    // -------- Phase 1: sP[lr][c] = dot64(Q[r0+lr], K[c])  (FFMA2) --------
    {
        const int c    = t & 127;
        const int hseg = t >> 7;             // 32 rows each
        unsigned long long kc[32];
        {
            const ulonglong2* kp = (const ulonglong2*)(sK + c * KPAD);
            #pragma unroll
            for (int i = 0; i < 16; i++) {
                ulonglong2 v = kp[i];
                kc[2 * i] = v.x; kc[2 * i + 1] = v.y;
            }
        }
        const int lr0 = hseg * 32;
        for (int lr = lr0; lr < lr0 + 32; ++lr) {
            const ulonglong2* qp = (const ulonglong2*)(sQ + lr * EE); // broadcast
            unsigned long long acc = 0ull;   // f32x2 {0,0}
            #pragma unroll
            for (int i = 0; i < 16; i++) {
                ulonglong2 qv = qp[i];
                ffma2(acc, qv.x, kc[2 * i]);
                ffma2(acc, qv.y, kc[2 * i + 1]);
            }
            sP[lr * LL + c] = unpack_sum(acc);
        }
    }
    __syncthreads();

    // -------- Phase 2: row softmax + group-mean atomic accumulation --------
    {
        const int warp = t >> 5, lane = t & 31;
        const int g = b >> 4;
        float* accb = g_acc + ((size_t)(g * HH + h) * LL) * LL;
        const float scale = 0.125f;          // 1/sqrt(64)
        const float gsc   = 1.0f / 16.0f;

        for (int r = warp; r < 64; r += 8) {
            float* row = sP + r * LL;
            float4 v = *(float4*)(row + 4 * lane);       // conflict-free
            float m = fmaxf(fmaxf(v.x, v.y), fmaxf(v.z, v.w));
            #pragma unroll
            for (int o = 16; o; o >>= 1)
                m = fmaxf(m, __shfl_xor_sync(0xffffffffu, m, o));
            float4 e;
            e.x = __expf(scale * (v.x - m));
            e.y = __expf(scale * (v.y - m));
            e.z = __expf(scale * (v.z - m));
            e.w = __expf(scale * (v.w - m));
            float s = e.x + e.y + e.z + e.w;
            #pragma unroll
            for (int o = 16; o; o >>= 1)
                s += __shfl_xor_sync(0xffffffffu, s, o);
            float inv = 1.0f / s;
            e.x *= inv; e.y *= inv; e.z *= inv; e.w *= inv;
            *(float4*)(row + 4 * lane) = e;
            float* ab = accb + (size_t)(r0 + r) * LL + 4 * lane;
            atomicAdd(ab + 0, e.x * gsc);
            atomicAdd(ab + 1, e.y * gsc);
            atomicAdd(ab + 2, e.z * gsc);
            atomicAdd(ab + 3, e.w * gsc);
        }
    }
    __syncthreads();

    // -------- Phase 3: outV[r][d] = sum_s P[r][s] * V[s][d]  (FFMA2) --------
    {
        const int d  = t & 63;
        const int rg = t >> 6;               // 4 groups of 16 rows
        unsigned long long acc2[16];
        #pragma unroll
        for (int j = 0; j < 16; j++) acc2[j] = 0ull;

        const float* pbase = sP + (rg * 16) * LL;
        for (int s = 0; s < LL; s += 4) {
            float w0 = sV[(s + 0) * EE + d];             // conflict-free
            float w1 = sV[(s + 1) * EE + d];
            float w2 = sV[(s + 2) * EE + d];
            float w3 = sV[(s + 3) * EE + d];
            unsigned long long w01 = pack2(w0, w1);
            unsigned long long w23 = pack2(w2, w3);
            #pragma unroll
            for (int j = 0; j < 16; j++) {
                ulonglong2 p2 = *(const ulonglong2*)(pbase + j * LL + s); // broadcast
                ffma2(acc2[j], p2.x, w01);
                ffma2(acc2[j], p2.y, w23);
            }
        }
        #pragma unroll
        for (int j = 0; j < 16; j++) {
            int r = r0 + rg * 16 + j;
            outV[((size_t)(b * LL + r) * HH + h) * EE + d] = unpack_sum(acc2[j]);
        }
    }
}

// ---------------------------------------------------------------------------
// Kernel 2: tiled series write. One CTA per output row; pure write bandwidth.
// ---------------------------------------------------------------------------
__global__ void __launch_bounds__(256) tile_kernel(float* __restrict__ outS) {
    const int rowid = blockIdx.x;            // [0, 32768)
    const int i  = rowid & (WIN - 1);
    const int gh = rowid >> 11;
    const float* src = g_acc + ((size_t)gh * LL + (i & (LL - 1))) * LL;
    const int t = threadIdx.x;

    float4 v = *(const float4*)(src + ((4 * t) & (LL - 1)));
    float4* d4 = (float4*)(outS + (size_t)rowid * WIN);
    d4[t]       = v;
    d4[t + 256] = v;
}

// ---------------------------------------------------------------------------
extern "C" void kernel_launch(void* const* d_in, const int* in_sizes, int n_in,
                              void* d_out, int out_size) {
    (void)in_sizes; (void)n_in; (void)out_size;
    const float* Q = (const float*)d_in[0];
    const float* K = (const float*)d_in[1];
    const float* V = (const float*)d_in[2];
    // d_in[3] = patch_index (always 0 -> p=16 tile/mean branch).

    float* outV = (float*)d_out;                       // [32,128,8,64]
    float* outS = outV + (size_t)BB * LL * HH * EE;    // [2,8,2048,2048]

    const int smem = 29184 * (int)sizeof(float);       // 114 KB
    cudaFuncSetAttribute(attn_kernel,
                         cudaFuncAttributeMaxDynamicSharedMemorySize, smem);

    zero_acc_kernel<<<GG * HH * LL * LL / 1024, 256>>>();
    attn_kernel<<<BB * HH * 2, 256, smem>>>(Q, K, V, outV);
    tile_kernel<<<GG * HH * WIN, 256>>>(outS);
}

// round 4
// speedup vs baseline: 1.2622x; 1.2622x over previous
#include <cuda_runtime.h>
#include <cstdint>

// Problem constants
#define BB  32
#define LL  128
#define HH  8
#define EE  64
#define PP  16
#define GG  2          // BB / PP
#define WIN 2048

// smem padding (floats per row) chosen for conflict-free mma fragment LDS
#define QP  68
#define KP  68
#define VP  72
#define SPP 132

// Group-mean series accumulator: [G, H, L, L] = 4 MB.
__device__ float g_acc[GG * HH * LL * LL];

// ---------------------------------------------------------------------------
__global__ void zero_acc_kernel() {
    int i = blockIdx.x * 256 + threadIdx.x;
    ((float4*)g_acc)[i] = make_float4(0.f, 0.f, 0.f, 0.f);
}

// ---------------------------------------------------------------------------
// tf32 helpers (3xTF32 error-compensated path)
// ---------------------------------------------------------------------------
__device__ __forceinline__ uint32_t f2tf32(float x) {
    uint32_t r;
    asm("cvt.rna.tf32.f32 %0, %1;" : "=r"(r) : "f"(x));
    return r;
}
__device__ __forceinline__ void split_tf32(float x, uint32_t& hi, uint32_t& lo) {
    hi = f2tf32(x);
    lo = f2tf32(x - __uint_as_float(hi));
}
__device__ __forceinline__ void mma_tf32(float c[4],
                                         uint32_t a0, uint32_t a1, uint32_t a2, uint32_t a3,
                                         uint32_t b0, uint32_t b1) {
    asm("mma.sync.aligned.m16n8k8.row.col.f32.tf32.tf32.f32 "
        "{%0,%1,%2,%3}, {%4,%5,%6,%7}, {%8,%9}, {%0,%1,%2,%3};"
        : "+f"(c[0]), "+f"(c[1]), "+f"(c[2]), "+f"(c[3])
        : "r"(a0), "r"(a1), "r"(a2), "r"(a3), "r"(b0), "r"(b1));
}

// ---------------------------------------------------------------------------
// Attention: one CTA per (b, h). 256 threads = 8 warps.
//   smem floats: sQ[128][68] | sK[128][68] | sV[128][72] | sP[128][132]
//   Phase 1: S = (Q*scale) K^T via 3xTF32 mma  (warp w owns rows 16w..16w+15)
//   Phase 2: softmax rows + atomicAdd group mean into g_acc
//   Phase 3: O = P V  via 3xTF32 mma
// ---------------------------------------------------------------------------
__global__ void __launch_bounds__(256, 1) attn_kernel(
    const float* __restrict__ Q, const float* __restrict__ K,
    const float* __restrict__ V, float* __restrict__ outV)
{
    extern __shared__ float sm[];
    float* sQ = sm;                               // 128*68 = 8704
    float* sK = sm + 128 * QP;                    // 8704
    float* sV = sm + 128 * (QP + KP);             // 128*72 = 9216
    float* sP = sm + 128 * (QP + KP + VP);        // 128*132 = 16896

    const int b = blockIdx.x >> 3;
    const int h = blockIdx.x & 7;
    const int t = threadIdx.x;
    const int w    = t >> 5;
    const int lane = t & 31;
    const int g    = lane >> 2;     // group id (row within fragment)
    const int tq   = lane & 3;      // thread-in-group (col within fragment)
    const int m0   = w * 16;        // this warp's row block

    // ---- stage Q (pre-scaled by 1/sqrt(E)), K, V
    const size_t base = ((size_t)b * LL * HH + h) * EE;
    const float4* q4 = (const float4*)(Q + base);
    const float4* k4 = (const float4*)(K + base);
    const float4* v4 = (const float4*)(V + base);
    const float scale = 0.125f;     // 1/sqrt(64)
    for (int i = t; i < 2048; i += 256) {
        int row = i >> 4, c4 = i & 15;
        float4 qv = q4[row * 128 + c4];
        qv.x *= scale; qv.y *= scale; qv.z *= scale; qv.w *= scale;
        ((float4*)(sQ + row * QP))[c4] = qv;
        ((float4*)(sK + row * KP))[c4] = k4[row * 128 + c4];
        ((float4*)(sV + row * VP))[c4] = v4[row * 128 + c4];
    }
    __syncthreads();

    // -------- Phase 1: S[m0..m0+16][0..128] --------
    {
        uint32_t Ahi[8][4], Alo[8][4];
        #pragma unroll
        for (int kk = 0; kk < 8; kk++) {
            int k0 = kk * 8;
            split_tf32(sQ[(m0 + g)     * QP + k0 + tq],     Ahi[kk][0], Alo[kk][0]);
            split_tf32(sQ[(m0 + g + 8) * QP + k0 + tq],     Ahi[kk][1], Alo[kk][1]);
            split_tf32(sQ[(m0 + g)     * QP + k0 + tq + 4], Ahi[kk][2], Alo[kk][2]);
            split_tf32(sQ[(m0 + g + 8) * QP + k0 + tq + 4], Ahi[kk][3], Alo[kk][3]);
        }
        for (int nt = 0; nt < 16; nt++) {
            int n0 = nt * 8;
            uint32_t Bhi[8][2], Blo[8][2];
            #pragma unroll
            for (int kk = 0; kk < 8; kk++) {
                int k0 = kk * 8;
                split_tf32(sK[(n0 + g) * KP + k0 + tq],     Bhi[kk][0], Blo[kk][0]);
                split_tf32(sK[(n0 + g) * KP + k0 + tq + 4], Bhi[kk][1], Blo[kk][1]);
            }
            float c[4] = {0.f, 0.f, 0.f, 0.f};
            #pragma unroll
            for (int kk = 0; kk < 8; kk++) {
                mma_tf32(c, Alo[kk][0], Alo[kk][1], Alo[kk][2], Alo[kk][3],
                            Bhi[kk][0], Bhi[kk][1]);
                mma_tf32(c, Ahi[kk][0], Ahi[kk][1], Ahi[kk][2], Ahi[kk][3],
                            Blo[kk][0], Blo[kk][1]);
                mma_tf32(c, Ahi[kk][0], Ahi[kk][1], Ahi[kk][2], Ahi[kk][3],
                            Bhi[kk][0], Bhi[kk][1]);
            }
            *(float2*)(sP + (m0 + g)     * SPP + n0 + 2 * tq) = make_float2(c[0], c[1]);
            *(float2*)(sP + (m0 + g + 8) * SPP + n0 + 2 * tq) = make_float2(c[2], c[3]);
        }
    }
    __syncthreads();

    // -------- Phase 2: row softmax + group-mean atomics --------
    {
        const int grp = b >> 4;
        float* accb = g_acc + ((size_t)(grp * HH + h) * LL) * LL;
        const float gsc = 1.0f / 16.0f;

        for (int r = w; r < LL; r += 8) {
            float* row = sP + r * SPP;
            float4 v = *(float4*)(row + 4 * lane);
            float m = fmaxf(fmaxf(v.x, v.y), fmaxf(v.z, v.w));
            #pragma unroll
            for (int o = 16; o; o >>= 1)
                m = fmaxf(m, __shfl_xor_sync(0xffffffffu, m, o));
            float4 e;
            e.x = __expf(v.x - m);
            e.y = __expf(v.y - m);
            e.z = __expf(v.z - m);
            e.w = __expf(v.w - m);
            float s = e.x + e.y + e.z + e.w;
            #pragma unroll
            for (int o = 16; o; o >>= 1)
                s += __shfl_xor_sync(0xffffffffu, s, o);
            float inv = 1.0f / s;
            e.x *= inv; e.y *= inv; e.z *= inv; e.w *= inv;
            *(float4*)(row + 4 * lane) = e;
            float* ab = accb + (size_t)r * LL + 4 * lane;
            atomicAdd(ab + 0, e.x * gsc);
            atomicAdd(ab + 1, e.y * gsc);
            atomicAdd(ab + 2, e.z * gsc);
            atomicAdd(ab + 3, e.w * gsc);
        }
    }
    __syncthreads();

    // -------- Phase 3: O[m0..m0+16][0..64] = P V --------
    {
        float acc[8][4];
        #pragma unroll
        for (int nt = 0; nt < 8; nt++)
            #pragma unroll
            for (int j = 0; j < 4; j++) acc[nt][j] = 0.f;

        for (int kk = 0; kk < 16; kk++) {
            int k0 = kk * 8;
            uint32_t ahi[4], alo[4];
            split_tf32(sP[(m0 + g)     * SPP + k0 + tq],     ahi[0], alo[0]);
            split_tf32(sP[(m0 + g + 8) * SPP + k0 + tq],     ahi[1], alo[1]);
            split_tf32(sP[(m0 + g)     * SPP + k0 + tq + 4], ahi[2], alo[2]);
            split_tf32(sP[(m0 + g + 8) * SPP + k0 + tq + 4], ahi[3], alo[3]);
            #pragma unroll
            for (int nt = 0; nt < 8; nt++) {
                int n0 = nt * 8;
                uint32_t bhi0, blo0, bhi1, blo1;
                split_tf32(sV[(k0 + tq)     * VP + n0 + g], bhi0, blo0);
                split_tf32(sV[(k0 + tq + 4) * VP + n0 + g], bhi1, blo1);
                mma_tf32(acc[nt], alo[0], alo[1], alo[2], alo[3], bhi0, bhi1);
                mma_tf32(acc[nt], ahi[0], ahi[1], ahi[2], ahi[3], blo0, blo1);
                mma_tf32(acc[nt], ahi[0], ahi[1], ahi[2], ahi[3], bhi0, bhi1);
            }
        }
        // store O: row r, col c -> outV[((b*128 + r)*8 + h)*64 + c]
        #pragma unroll
        for (int nt = 0; nt < 8; nt++) {
            int n0 = nt * 8;
            size_t r0a = ((size_t)(b * LL + m0 + g)     * HH + h) * EE + n0 + 2 * tq;
            size_t r1a = ((size_t)(b * LL + m0 + g + 8) * HH + h) * EE + n0 + 2 * tq;
            *(float2*)(outV + r0a) = make_float2(acc[nt][0], acc[nt][1]);
            *(float2*)(outV + r1a) = make_float2(acc[nt][2], acc[nt][3]);
        }
    }
}

// ---------------------------------------------------------------------------
// Tiled series write: one CTA per output row; pure write bandwidth.
// ---------------------------------------------------------------------------
__global__ void __launch_bounds__(256) tile_kernel(float* __restrict__ outS) {
    const int rowid = blockIdx.x;            // [0, 32768)
    const int i  = rowid & (WIN - 1);
    const int gh = rowid >> 11;
    const float* src = g_acc + ((size_t)gh * LL + (i & (LL - 1))) * LL;
    const int t = threadIdx.x;

    float4 v = *(const float4*)(src + ((4 * t) & (LL - 1)));
    float4* d4 = (float4*)(outS + (size_t)rowid * WIN);
    d4[t]       = v;
    d4[t + 256] = v;
}

// ---------------------------------------------------------------------------
extern "C" void kernel_launch(void* const* d_in, const int* in_sizes, int n_in,
                              void* d_out, int out_size) {
    (void)in_sizes; (void)n_in; (void)out_size;
    const float* Q = (const float*)d_in[0];
    const float* K = (const float*)d_in[1];
    const float* V = (const float*)d_in[2];
    // d_in[3] = patch_index (always 0 -> p=16 tile/mean branch).

    float* outV = (float*)d_out;                       // [32,128,8,64]
    float* outS = outV + (size_t)BB * LL * HH * EE;    // [2,8,2048,2048]

    const int smem = 128 * (QP + KP + VP + SPP) * (int)sizeof(float); // 174080
    cudaFuncSetAttribute(attn_kernel,
                         cudaFuncAttributeMaxDynamicSharedMemorySize, smem);

    zero_acc_kernel<<<GG * HH * LL * LL / 1024, 256>>>();
    attn_kernel<<<BB * HH, 256, smem>>>(Q, K, V, outV);
    tile_kernel<<<GG * HH * WIN, 256>>>(outS);
}